// round 5
// baseline (speedup 1.0000x reference)
#include <cuda_runtime.h>
#include <cuda_bf16.h>
#include <math.h>

#define S_WORDS 2048
#define LMAX    16
#define CE      256
#define WE      512
#define HDIM    1024
#define GC      (4*CE)     // 1024 gate rows, char LSTM
#define GW      (4*HDIM)   // 4096 gate rows, word LSTM
#define KC      (2*CE)     // 512  (x | h) for char LSTM
#define KW      (WE+CE)    // 768  (we | char_feat)
#define NBLK_WL 128        // persistent blocks for word LSTM (<= 148 SMs)

// ---------------- device scratch (no allocations allowed) ----------------
__device__ float g_WcT[KC*GC];        // [k=512][g=1024] transposed char weights
__device__ float g_WihwT[KW*GW];      // [k=768][g=4096] transposed word input weights
__device__ float g_lasth[S_WORDS*CE]; // char-LSTM output feature per word
__device__ float g_GXw[S_WORDS*GW];   // precomputed x-part of word-LSTM gates (+bias)
__device__ float g_hbuf[2*HDIM];      // word-LSTM h broadcast, double-buffered
__device__ int   g_flag[NBLK_WL];     // per-block step counters (distinct addresses!)

__device__ __forceinline__ float sigf(float x) { return 1.f / (1.f + __expf(-x)); }

// ---------------- prep: transpose weights, reset flags ----------------
__global__ void prep_c(const float* __restrict__ Wih_c, const float* __restrict__ Whh_c) {
    int idx = blockIdx.x * blockDim.x + threadIdx.x;
    if (idx >= KC * GC) return;
    int k = idx / GC, g = idx % GC;
    g_WcT[idx] = (k < CE) ? Wih_c[g * CE + k] : Whh_c[g * CE + (k - CE)];
}

__global__ void prep_w(const float* __restrict__ Wih_w) {
    int idx = blockIdx.x * blockDim.x + threadIdx.x;
    if (idx < NBLK_WL) g_flag[idx] = 0;
    if (idx >= KW * GW) return;
    int k = idx / GW, g = idx % GW;
    g_WihwT[idx] = Wih_w[g * KW + k];
}

// ---------------- char LSTM: 8 words per block, 16 timesteps ----------------
// SMEM: xh[8][512] (x|h per word), gates[8][1024]
__global__ void char_lstm(const int*   __restrict__ char_idxs,
                          const int*   __restrict__ char_lens,
                          const float* __restrict__ char_emb,
                          const float* __restrict__ bih_c,
                          const float* __restrict__ bhh_c)
{
    extern __shared__ float sm[];
    float* xh    = sm;            // 8*512
    float* gates = sm + 8 * KC;   // 8*1024
    const int tid   = threadIdx.x;      // 0..255
    const int wbase = blockIdx.x * 8;

    float bias[4];
#pragma unroll
    for (int q = 0; q < 4; q++) bias[q] = bih_c[4 * tid + q] + bhh_c[4 * tid + q];

    float c[8];
    int   len[8];
#pragma unroll
    for (int w = 0; w < 8; w++) {
        c[w]  = 0.f;
        len[w] = char_lens[wbase + w];
        xh[w * KC + CE + tid] = 0.f;   // h = 0
    }
    __syncthreads();

    const float4* Wp = reinterpret_cast<const float4*>(g_WcT) + tid;  // column block 4*tid

    for (int t = 0; t < LMAX; t++) {
        // gather x_t for the 8 words
#pragma unroll
        for (int w = 0; w < 8; w++) {
            int ci = char_idxs[(wbase + w) * LMAX + t];
            xh[w * KC + tid] = char_emb[ci * CE + tid];
        }
        __syncthreads();

        float acc[8][4];
#pragma unroll
        for (int w = 0; w < 8; w++)
#pragma unroll
            for (int q = 0; q < 4; q++) acc[w][q] = 0.f;

#pragma unroll 4
        for (int k = 0; k < KC; k++) {
            float4 wv = Wp[k * (GC / 4)];
#pragma unroll
            for (int w = 0; w < 8; w++) {
                float xv = xh[w * KC + k];
                acc[w][0] = fmaf(wv.x, xv, acc[w][0]);
                acc[w][1] = fmaf(wv.y, xv, acc[w][1]);
                acc[w][2] = fmaf(wv.z, xv, acc[w][2]);
                acc[w][3] = fmaf(wv.w, xv, acc[w][3]);
            }
        }
#pragma unroll
        for (int w = 0; w < 8; w++) {
            reinterpret_cast<float4*>(gates + w * GC)[tid] =
                make_float4(acc[w][0] + bias[0], acc[w][1] + bias[1],
                            acc[w][2] + bias[2], acc[w][3] + bias[3]);
        }
        __syncthreads();

        // cell update: thread tid owns hidden unit tid (torch gate order i,f,g,o)
#pragma unroll
        for (int w = 0; w < 8; w++) {
            float ig = gates[w * GC +            tid];
            float fg = gates[w * GC +     CE +   tid];
            float gg = gates[w * GC + 2 * CE +   tid];
            float og = gates[w * GC + 3 * CE +   tid];
            float cn = sigf(fg) * c[w] + sigf(ig) * tanhf(gg);
            float hn = sigf(og) * tanhf(cn);
            c[w] = cn;
            xh[w * KC + CE + tid] = hn;
            if (t == len[w] - 1) g_lasth[(wbase + w) * CE + tid] = hn;
        }
        __syncthreads();
    }
}

// ---------------- word-LSTM input GEMM: GXw = [we|last] @ Wih_w^T + bias ----------------
__global__ void word_gemm(const int*   __restrict__ word_idxs,
                          const float* __restrict__ word_emb,
                          const float* __restrict__ bih_w,
                          const float* __restrict__ bhh_w)
{
    extern __shared__ float xw[];   // [8][768]
    const int tid   = threadIdx.x;           // 0..255
    const int wbase = blockIdx.x * 8;
    const int gq    = blockIdx.y * 256 + tid; // float4 column index 0..1023

#pragma unroll
    for (int w = 0; w < 8; w++) {
        int wi = word_idxs[wbase + w];
        xw[w * KW +       tid] = word_emb[wi * WE +       tid];
        xw[w * KW + 256 + tid] = word_emb[wi * WE + 256 + tid];
        xw[w * KW + 512 + tid] = g_lasth[(wbase + w) * CE + tid];
    }
    __syncthreads();

    const int gbase = 4 * gq;
    float bias[4];
#pragma unroll
    for (int q = 0; q < 4; q++) bias[q] = bih_w[gbase + q] + bhh_w[gbase + q];

    float acc[8][4];
#pragma unroll
    for (int w = 0; w < 8; w++)
#pragma unroll
        for (int q = 0; q < 4; q++) acc[w][q] = 0.f;

    const float4* Wp = reinterpret_cast<const float4*>(g_WihwT) + gq;
#pragma unroll 4
    for (int k = 0; k < KW; k++) {
        float4 wv = Wp[k * (GW / 4)];
#pragma unroll
        for (int w = 0; w < 8; w++) {
            float xv = xw[w * KW + k];
            acc[w][0] = fmaf(wv.x, xv, acc[w][0]);
            acc[w][1] = fmaf(wv.y, xv, acc[w][1]);
            acc[w][2] = fmaf(wv.z, xv, acc[w][2]);
            acc[w][3] = fmaf(wv.w, xv, acc[w][3]);
        }
    }
#pragma unroll
    for (int w = 0; w < 8; w++) {
        reinterpret_cast<float4*>(g_GXw + (size_t)(wbase + w) * GW)[gq] =
            make_float4(acc[w][0] + bias[0], acc[w][1] + bias[1],
                        acc[w][2] + bias[2], acc[w][3] + bias[3]);
    }
}

// ---------------- word LSTM recurrence: persistent, register-resident Whh ----------------
// 128 blocks x 256 threads. Warp y of block b owns hidden unit u = 8b + y.
// Barrier: per-block flag array (distinct addresses), parallel polling.
// h broadcast: double-buffered g_hbuf, coalesced ld.global.cg reload into smem.
__global__ void __launch_bounds__(256, 1) word_lstm(const float* __restrict__ Whh_w,
                                                    float*       __restrict__ out)
{
    __shared__ float hs[HDIM];
    const int tid  = threadIdx.x;
    const int lane = tid & 31;
    const int y    = tid >> 5;
    const int u    = blockIdx.x * 8 + y;

    float w0[32], w1[32], w2[32], w3[32];
#pragma unroll
    for (int i = 0; i < 32; i++) {
        w0[i] = Whh_w[(size_t)(0 * HDIM + u) * HDIM + i * 32 + lane];
        w1[i] = Whh_w[(size_t)(1 * HDIM + u) * HDIM + i * 32 + lane];
        w2[i] = Whh_w[(size_t)(2 * HDIM + u) * HDIM + i * 32 + lane];
        w3[i] = Whh_w[(size_t)(3 * HDIM + u) * HDIM + i * 32 + lane];
    }
    float c = 0.f;

    for (int s = 0; s < S_WORDS; s++) {
        // prefetch gx_s before the barrier wait (independent of h)
        const float* gx = g_GXw + (size_t)s * GW;
        float gi0 = gx[u];
        float gf0 = gx[HDIM     + u];
        float gg0 = gx[2*HDIM   + u];
        float go0 = gx[3*HDIM   + u];

        float a0 = 0.f, a1 = 0.f, a2 = 0.f, a3 = 0.f;
        if (s > 0) {
            // wait until every block has published h_{s-1}
            if (tid < NBLK_WL) {
                const volatile int* f = g_flag + tid;
                while (*f < s) { }
            }
            __syncthreads();
            // coalesced, pipelined reload of h_{s-1} from L2 into smem
            const float* hb = g_hbuf + ((s - 1) & 1) * HDIM;
#pragma unroll
            for (int k = tid; k < HDIM; k += 256) {
                float v;
                asm volatile("ld.global.cg.f32 %0, [%1];" : "=f"(v) : "l"(hb + k));
                hs[k] = v;
            }
            __syncthreads();

#pragma unroll
            for (int i = 0; i < 32; i++) {
                float hv = hs[i * 32 + lane];
                a0 = fmaf(w0[i], hv, a0);
                a1 = fmaf(w1[i], hv, a1);
                a2 = fmaf(w2[i], hv, a2);
                a3 = fmaf(w3[i], hv, a3);
            }
        }
#pragma unroll
        for (int off = 16; off > 0; off >>= 1) {
            a0 += __shfl_xor_sync(0xffffffffu, a0, off);
            a1 += __shfl_xor_sync(0xffffffffu, a1, off);
            a2 += __shfl_xor_sync(0xffffffffu, a2, off);
            a3 += __shfl_xor_sync(0xffffffffu, a3, off);
        }

        float cn = sigf(gf0 + a1) * c + sigf(gi0 + a0) * tanhf(gg0 + a2);
        c = cn;
        float h = sigf(go0 + a3) * tanhf(cn);

        if (lane == 0) {
            out[(size_t)s * HDIM + u] = h;
            g_hbuf[(s & 1) * HDIM + u] = h;
            __threadfence();    // publish h before this block's flag store
        }
        __syncthreads();
        if (s < S_WORDS - 1 && tid == 0) {
            *((volatile int*)&g_flag[blockIdx.x]) = s + 1;
        }
    }
}

// ---------------- launch ----------------
extern "C" void kernel_launch(void* const* d_in, const int* in_sizes, int n_in,
                              void* d_out, int out_size)
{
    const int*   word_idxs = (const int*)  d_in[0];
    const int*   char_idxs = (const int*)  d_in[1];
    const int*   char_lens = (const int*)  d_in[2];
    const float* char_emb  = (const float*)d_in[3];
    const float* word_emb  = (const float*)d_in[4];
    const float* Wih_c     = (const float*)d_in[5];
    const float* Whh_c     = (const float*)d_in[6];
    const float* bih_c     = (const float*)d_in[7];
    const float* bhh_c     = (const float*)d_in[8];
    const float* Wih_w     = (const float*)d_in[9];
    const float* Whh_w     = (const float*)d_in[10];
    const float* bih_w     = (const float*)d_in[11];
    const float* bhh_w     = (const float*)d_in[12];
    float* out = (float*)d_out;

    const int char_smem = (8 * KC + 8 * GC) * (int)sizeof(float);   // 49152 B
    const int gemm_smem = 8 * KW * (int)sizeof(float);              // 24576 B
    cudaFuncSetAttribute(char_lstm, cudaFuncAttributeMaxDynamicSharedMemorySize, char_smem);
    cudaFuncSetAttribute(word_gemm, cudaFuncAttributeMaxDynamicSharedMemorySize, gemm_smem);

    prep_c<<<(KC * GC + 255) / 256, 256>>>(Wih_c, Whh_c);
    prep_w<<<(KW * GW + 255) / 256, 256>>>(Wih_w);   // also resets g_flag

    char_lstm<<<S_WORDS / 8, 256, char_smem>>>(char_idxs, char_lens, char_emb, bih_c, bhh_c);

    word_gemm<<<dim3(S_WORDS / 8, 4), 256, gemm_smem>>>(word_idxs, word_emb, bih_w, bhh_w);

    word_lstm<<<NBLK_WL, 256>>>(Whh_w, out);
}

// round 6
// speedup vs baseline: 1.0001x; 1.0001x over previous
#include <cuda_runtime.h>
#include <cuda_bf16.h>
#include <math.h>

#define S_WORDS 2048
#define LMAX    16
#define CE      256
#define WE      512
#define HDIM    1024
#define GC      (4*CE)     // 1024 gate rows, char LSTM
#define GW      (4*HDIM)   // 4096 gate rows, word LSTM
#define KC      (2*CE)     // 512  (x | h) for char LSTM
#define KW      (WE+CE)    // 768  (we | char_feat)
#define NBLK_WL 128        // persistent blocks for word LSTM (<= 148 SMs)

// ---------------- device scratch (no allocations allowed) ----------------
__device__ float g_WcT[KC*GC];        // [k=512][g=1024] transposed char weights
__device__ float g_WihwT[KW*GW];      // [k=768][g=4096] transposed word input weights
__device__ float g_lasth[S_WORDS*CE]; // char-LSTM output feature per word
__device__ float g_GXw[S_WORDS*GW];   // precomputed x-part of word-LSTM gates (+bias)
__device__ float g_hbuf[2*HDIM];      // word-LSTM h broadcast, double-buffered
__device__ int   g_flag[NBLK_WL];     // per-block step counters (distinct addresses!)

__device__ __forceinline__ float sigf(float x) { return 1.f / (1.f + __expf(-x)); }

// ---------------- prep: transpose weights, reset flags ----------------
__global__ void prep_c(const float* __restrict__ Wih_c, const float* __restrict__ Whh_c) {
    int idx = blockIdx.x * blockDim.x + threadIdx.x;
    if (idx >= KC * GC) return;
    int k = idx / GC, g = idx % GC;
    g_WcT[idx] = (k < CE) ? Wih_c[g * CE + k] : Whh_c[g * CE + (k - CE)];
}

__global__ void prep_w(const float* __restrict__ Wih_w) {
    int idx = blockIdx.x * blockDim.x + threadIdx.x;
    if (idx < NBLK_WL) g_flag[idx] = 0;
    if (idx >= KW * GW) return;
    int k = idx / GW, g = idx % GW;
    g_WihwT[idx] = Wih_w[g * KW + k];
}

// ---------------- char LSTM: 8 words per block, 16 timesteps ----------------
// SMEM: xh[8][512] (x|h per word), gates[8][1024]
__global__ void char_lstm(const int*   __restrict__ char_idxs,
                          const int*   __restrict__ char_lens,
                          const float* __restrict__ char_emb,
                          const float* __restrict__ bih_c,
                          const float* __restrict__ bhh_c)
{
    extern __shared__ float sm[];
    float* xh    = sm;            // 8*512
    float* gates = sm + 8 * KC;   // 8*1024
    const int tid   = threadIdx.x;      // 0..255
    const int wbase = blockIdx.x * 8;

    float bias[4];
#pragma unroll
    for (int q = 0; q < 4; q++) bias[q] = bih_c[4 * tid + q] + bhh_c[4 * tid + q];

    float c[8];
    int   len[8];
#pragma unroll
    for (int w = 0; w < 8; w++) {
        c[w]  = 0.f;
        len[w] = char_lens[wbase + w];
        xh[w * KC + CE + tid] = 0.f;   // h = 0
    }
    __syncthreads();

    const float4* Wp = reinterpret_cast<const float4*>(g_WcT) + tid;  // column block 4*tid

    for (int t = 0; t < LMAX; t++) {
        // gather x_t for the 8 words
#pragma unroll
        for (int w = 0; w < 8; w++) {
            int ci = char_idxs[(wbase + w) * LMAX + t];
            xh[w * KC + tid] = char_emb[ci * CE + tid];
        }
        __syncthreads();

        float acc[8][4];
#pragma unroll
        for (int w = 0; w < 8; w++)
#pragma unroll
            for (int q = 0; q < 4; q++) acc[w][q] = 0.f;

#pragma unroll 4
        for (int k = 0; k < KC; k++) {
            float4 wv = Wp[k * (GC / 4)];
#pragma unroll
            for (int w = 0; w < 8; w++) {
                float xv = xh[w * KC + k];
                acc[w][0] = fmaf(wv.x, xv, acc[w][0]);
                acc[w][1] = fmaf(wv.y, xv, acc[w][1]);
                acc[w][2] = fmaf(wv.z, xv, acc[w][2]);
                acc[w][3] = fmaf(wv.w, xv, acc[w][3]);
            }
        }
#pragma unroll
        for (int w = 0; w < 8; w++) {
            reinterpret_cast<float4*>(gates + w * GC)[tid] =
                make_float4(acc[w][0] + bias[0], acc[w][1] + bias[1],
                            acc[w][2] + bias[2], acc[w][3] + bias[3]);
        }
        __syncthreads();

        // cell update: thread tid owns hidden unit tid (torch gate order i,f,g,o)
#pragma unroll
        for (int w = 0; w < 8; w++) {
            float ig = gates[w * GC +            tid];
            float fg = gates[w * GC +     CE +   tid];
            float gg = gates[w * GC + 2 * CE +   tid];
            float og = gates[w * GC + 3 * CE +   tid];
            float cn = sigf(fg) * c[w] + sigf(ig) * tanhf(gg);
            float hn = sigf(og) * tanhf(cn);
            c[w] = cn;
            xh[w * KC + CE + tid] = hn;
            if (t == len[w] - 1) g_lasth[(wbase + w) * CE + tid] = hn;
        }
        __syncthreads();
    }
}

// ---------------- word-LSTM input GEMM: GXw = [we|last] @ Wih_w^T + bias ----------------
__global__ void word_gemm(const int*   __restrict__ word_idxs,
                          const float* __restrict__ word_emb,
                          const float* __restrict__ bih_w,
                          const float* __restrict__ bhh_w)
{
    extern __shared__ float xw[];   // [8][768]
    const int tid   = threadIdx.x;           // 0..255
    const int wbase = blockIdx.x * 8;
    const int gq    = blockIdx.y * 256 + tid; // float4 column index 0..1023

#pragma unroll
    for (int w = 0; w < 8; w++) {
        int wi = word_idxs[wbase + w];
        xw[w * KW +       tid] = word_emb[wi * WE +       tid];
        xw[w * KW + 256 + tid] = word_emb[wi * WE + 256 + tid];
        xw[w * KW + 512 + tid] = g_lasth[(wbase + w) * CE + tid];
    }
    __syncthreads();

    const int gbase = 4 * gq;
    float bias[4];
#pragma unroll
    for (int q = 0; q < 4; q++) bias[q] = bih_w[gbase + q] + bhh_w[gbase + q];

    float acc[8][4];
#pragma unroll
    for (int w = 0; w < 8; w++)
#pragma unroll
        for (int q = 0; q < 4; q++) acc[w][q] = 0.f;

    const float4* Wp = reinterpret_cast<const float4*>(g_WihwT) + gq;
#pragma unroll 4
    for (int k = 0; k < KW; k++) {
        float4 wv = Wp[k * (GW / 4)];
#pragma unroll
        for (int w = 0; w < 8; w++) {
            float xv = xw[w * KW + k];
            acc[w][0] = fmaf(wv.x, xv, acc[w][0]);
            acc[w][1] = fmaf(wv.y, xv, acc[w][1]);
            acc[w][2] = fmaf(wv.z, xv, acc[w][2]);
            acc[w][3] = fmaf(wv.w, xv, acc[w][3]);
        }
    }
#pragma unroll
    for (int w = 0; w < 8; w++) {
        reinterpret_cast<float4*>(g_GXw + (size_t)(wbase + w) * GW)[gq] =
            make_float4(acc[w][0] + bias[0], acc[w][1] + bias[1],
                        acc[w][2] + bias[2], acc[w][3] + bias[3]);
    }
}

// ---------------- word LSTM recurrence: persistent, register-resident Whh ----------------
// 128 blocks x 256 threads. Warp y of block b owns hidden unit u = 8b + y.
// Barrier: per-block flag array, polled by ONE warp per block (coalesced,
// acquire loads + nanosleep backoff). Producer: single gpu fence + relaxed store.
__global__ void __launch_bounds__(256, 1) word_lstm(const float* __restrict__ Whh_w,
                                                    float*       __restrict__ out)
{
    __shared__ float hs[HDIM];
    const int tid  = threadIdx.x;
    const int lane = tid & 31;
    const int y    = tid >> 5;
    const int u    = blockIdx.x * 8 + y;

    float w0[32], w1[32], w2[32], w3[32];
#pragma unroll
    for (int i = 0; i < 32; i++) {
        w0[i] = Whh_w[(size_t)(0 * HDIM + u) * HDIM + i * 32 + lane];
        w1[i] = Whh_w[(size_t)(1 * HDIM + u) * HDIM + i * 32 + lane];
        w2[i] = Whh_w[(size_t)(2 * HDIM + u) * HDIM + i * 32 + lane];
        w3[i] = Whh_w[(size_t)(3 * HDIM + u) * HDIM + i * 32 + lane];
    }
    float c = 0.f;

    for (int s = 0; s < S_WORDS; s++) {
        // prefetch gx_s before the barrier wait (independent of h)
        const float* gx = g_GXw + (size_t)s * GW;
        float gi0 = gx[u];
        float gf0 = gx[HDIM     + u];
        float gg0 = gx[2*HDIM   + u];
        float go0 = gx[3*HDIM   + u];

        float a0 = 0.f, a1 = 0.f, a2 = 0.f, a3 = 0.f;
        if (s > 0) {
            // ONE warp polls all 128 flags: lane checks flags {lane, lane+32, ...}
            if (tid < 32) {
#pragma unroll
                for (int j = 0; j < 4; j++) {
                    const int* f = g_flag + j * 32 + tid;
                    int v;
                    asm volatile("ld.acquire.gpu.global.s32 %0, [%1];" : "=r"(v) : "l"(f));
                    while (v < s) {
                        __nanosleep(40);
                        asm volatile("ld.acquire.gpu.global.s32 %0, [%1];" : "=r"(v) : "l"(f));
                    }
                }
            }
            __syncthreads();
            // coalesced, pipelined reload of h_{s-1} from L2 into smem
            const float* hb = g_hbuf + ((s - 1) & 1) * HDIM;
#pragma unroll
            for (int k = 0; k < 4; k++)
                hs[k * 256 + tid] = __ldcg(hb + k * 256 + tid);
            __syncthreads();

#pragma unroll
            for (int i = 0; i < 32; i++) {
                float hv = hs[i * 32 + lane];
                a0 = fmaf(w0[i], hv, a0);
                a1 = fmaf(w1[i], hv, a1);
                a2 = fmaf(w2[i], hv, a2);
                a3 = fmaf(w3[i], hv, a3);
            }
        }
#pragma unroll
        for (int off = 16; off > 0; off >>= 1) {
            a0 += __shfl_xor_sync(0xffffffffu, a0, off);
            a1 += __shfl_xor_sync(0xffffffffu, a1, off);
            a2 += __shfl_xor_sync(0xffffffffu, a2, off);
            a3 += __shfl_xor_sync(0xffffffffu, a3, off);
        }

        float cn = sigf(gf0 + a1) * c + sigf(gi0 + a0) * tanhf(gg0 + a2);
        c = cn;
        float h = sigf(go0 + a3) * tanhf(cn);

        if (lane == 0) {
            out[(size_t)s * HDIM + u] = h;
            g_hbuf[(s & 1) * HDIM + u] = h;
        }
        __syncthreads();
        if (s < S_WORDS - 1 && tid == 0) {
            __threadfence();   // cumulative gpu fence: all 8 h stores (ordered via bar) visible
            asm volatile("st.relaxed.gpu.global.s32 [%0], %1;"
                         :: "l"(g_flag + blockIdx.x), "r"(s + 1) : "memory");
        }
    }
}

// ---------------- launch ----------------
extern "C" void kernel_launch(void* const* d_in, const int* in_sizes, int n_in,
                              void* d_out, int out_size)
{
    const int*   word_idxs = (const int*)  d_in[0];
    const int*   char_idxs = (const int*)  d_in[1];
    const int*   char_lens = (const int*)  d_in[2];
    const float* char_emb  = (const float*)d_in[3];
    const float* word_emb  = (const float*)d_in[4];
    const float* Wih_c     = (const float*)d_in[5];
    const float* Whh_c     = (const float*)d_in[6];
    const float* bih_c     = (const float*)d_in[7];
    const float* bhh_c     = (const float*)d_in[8];
    const float* Wih_w     = (const float*)d_in[9];
    const float* Whh_w     = (const float*)d_in[10];
    const float* bih_w     = (const float*)d_in[11];
    const float* bhh_w     = (const float*)d_in[12];
    float* out = (float*)d_out;

    const int char_smem = (8 * KC + 8 * GC) * (int)sizeof(float);   // 49152 B
    const int gemm_smem = 8 * KW * (int)sizeof(float);              // 24576 B
    cudaFuncSetAttribute(char_lstm, cudaFuncAttributeMaxDynamicSharedMemorySize, char_smem);
    cudaFuncSetAttribute(word_gemm, cudaFuncAttributeMaxDynamicSharedMemorySize, gemm_smem);

    prep_c<<<(KC * GC + 255) / 256, 256>>>(Wih_c, Whh_c);
    prep_w<<<(KW * GW + 255) / 256, 256>>>(Wih_w);   // also resets g_flag

    char_lstm<<<S_WORDS / 8, 256, char_smem>>>(char_idxs, char_lens, char_emb, bih_c, bhh_c);

    word_gemm<<<dim3(S_WORDS / 8, 4), 256, gemm_smem>>>(word_idxs, word_emb, bih_w, bhh_w);

    word_lstm<<<NBLK_WL, 256>>>(Whh_w, out);
}

// round 7
// speedup vs baseline: 1.3962x; 1.3961x over previous
#include <cuda_runtime.h>
#include <cuda_bf16.h>
#include <math.h>

#define S_WORDS 2048
#define LMAX    16
#define CE      256
#define WE      512
#define HDIM    1024
#define GC      (4*CE)     // 1024 gate rows, char LSTM
#define GW      (4*HDIM)   // 4096 gate rows, word LSTM
#define KC      (2*CE)     // 512  (x | h) for char LSTM
#define KW      (WE+CE)    // 768  (we | char_feat)
#define NBLK_WL 128        // persistent blocks for word LSTM (<= 148 SMs)
#define CWPB    16         // words per block, char LSTM

// ---------------- device scratch (no allocations allowed) ----------------
__device__ float g_WcT[KC*GC];        // [k=512][g=1024] transposed char weights
__device__ float g_WihwT[KW*GW];      // [k=768][g=4096] transposed word input weights
__device__ float g_lasth[S_WORDS*CE]; // char-LSTM output feature per word
__device__ float g_GXw[S_WORDS*GW];   // precomputed x-part of word-LSTM gates (+bias)
__device__ float g_hbuf[2*HDIM];      // word-LSTM h broadcast, double-buffered
__device__ unsigned g_arrive;                 // monotonic arrival counter (own line)
__device__ __align__(128) int g_epoch[32];    // released step number (own line)

__device__ __forceinline__ float sigf(float x) { return 1.f / (1.f + __expf(-x)); }

// ---------------- prep: transpose weights, reset barrier state ----------------
__global__ void prep_c(const float* __restrict__ Wih_c, const float* __restrict__ Whh_c) {
    int idx = blockIdx.x * blockDim.x + threadIdx.x;
    if (idx >= KC * GC) return;
    int k = idx / GC, g = idx % GC;
    g_WcT[idx] = (k < CE) ? Wih_c[g * CE + k] : Whh_c[g * CE + (k - CE)];
}

__global__ void prep_w(const float* __restrict__ Wih_w) {
    int idx = blockIdx.x * blockDim.x + threadIdx.x;
    if (idx == 0) { g_arrive = 0u; g_epoch[0] = 0; }
    if (idx >= KW * GW) return;
    int k = idx / GW, g = idx % GW;
    g_WihwT[idx] = Wih_w[g * KW + k];
}

// ---------------- char LSTM: 16 words per block, 16 timesteps ----------------
// SMEM: xh[16][512] (x|h per word), gates[16][1024]   (96 KB)
__global__ void __launch_bounds__(256) char_lstm(
    const int*   __restrict__ char_idxs,
    const int*   __restrict__ char_lens,
    const float* __restrict__ char_emb,
    const float* __restrict__ bih_c,
    const float* __restrict__ bhh_c)
{
    extern __shared__ float sm[];
    float* xh    = sm;               // CWPB*512
    float* gates = sm + CWPB * KC;   // CWPB*1024
    const int tid   = threadIdx.x;      // 0..255
    const int wbase = blockIdx.x * CWPB;

    float bias[4];
#pragma unroll
    for (int q = 0; q < 4; q++) bias[q] = bih_c[4 * tid + q] + bhh_c[4 * tid + q];

    float c[CWPB];
    int   len[CWPB];
#pragma unroll
    for (int w = 0; w < CWPB; w++) {
        c[w]  = 0.f;
        len[w] = char_lens[wbase + w];
        xh[w * KC + CE + tid] = 0.f;   // h = 0
    }
    __syncthreads();

    const float4* Wp = reinterpret_cast<const float4*>(g_WcT) + tid;  // column block 4*tid

    for (int t = 0; t < LMAX; t++) {
        // gather x_t for the words
#pragma unroll
        for (int w = 0; w < CWPB; w++) {
            int ci = char_idxs[(wbase + w) * LMAX + t];
            xh[w * KC + tid] = char_emb[ci * CE + tid];
        }
        __syncthreads();

        float acc[CWPB][4];
#pragma unroll
        for (int w = 0; w < CWPB; w++)
#pragma unroll
            for (int q = 0; q < 4; q++) acc[w][q] = 0.f;

#pragma unroll 2
        for (int k = 0; k < KC; k++) {
            float4 wv = Wp[k * (GC / 4)];
#pragma unroll
            for (int w = 0; w < CWPB; w++) {
                float xv = xh[w * KC + k];
                acc[w][0] = fmaf(wv.x, xv, acc[w][0]);
                acc[w][1] = fmaf(wv.y, xv, acc[w][1]);
                acc[w][2] = fmaf(wv.z, xv, acc[w][2]);
                acc[w][3] = fmaf(wv.w, xv, acc[w][3]);
            }
        }
#pragma unroll
        for (int w = 0; w < CWPB; w++) {
            reinterpret_cast<float4*>(gates + w * GC)[tid] =
                make_float4(acc[w][0] + bias[0], acc[w][1] + bias[1],
                            acc[w][2] + bias[2], acc[w][3] + bias[3]);
        }
        __syncthreads();

        // cell update: thread tid owns hidden unit tid (torch gate order i,f,g,o)
#pragma unroll
        for (int w = 0; w < CWPB; w++) {
            float ig = gates[w * GC +            tid];
            float fg = gates[w * GC +     CE +   tid];
            float gg = gates[w * GC + 2 * CE +   tid];
            float og = gates[w * GC + 3 * CE +   tid];
            float cn = sigf(fg) * c[w] + sigf(ig) * tanhf(gg);
            float hn = sigf(og) * tanhf(cn);
            c[w] = cn;
            xh[w * KC + CE + tid] = hn;
            if (t == len[w] - 1) g_lasth[(wbase + w) * CE + tid] = hn;
        }
        __syncthreads();
    }
}

// ---------------- word-LSTM input GEMM: GXw = [we|last] @ Wih_w^T + bias ----------------
__global__ void word_gemm(const int*   __restrict__ word_idxs,
                          const float* __restrict__ word_emb,
                          const float* __restrict__ bih_w,
                          const float* __restrict__ bhh_w)
{
    extern __shared__ float xw[];   // [8][768]
    const int tid   = threadIdx.x;           // 0..255
    const int wbase = blockIdx.x * 8;
    const int gq    = blockIdx.y * 256 + tid; // float4 column index 0..1023

#pragma unroll
    for (int w = 0; w < 8; w++) {
        int wi = word_idxs[wbase + w];
        xw[w * KW +       tid] = word_emb[wi * WE +       tid];
        xw[w * KW + 256 + tid] = word_emb[wi * WE + 256 + tid];
        xw[w * KW + 512 + tid] = g_lasth[(wbase + w) * CE + tid];
    }
    __syncthreads();

    const int gbase = 4 * gq;
    float bias[4];
#pragma unroll
    for (int q = 0; q < 4; q++) bias[q] = bih_w[gbase + q] + bhh_w[gbase + q];

    float acc[8][4];
#pragma unroll
    for (int w = 0; w < 8; w++)
#pragma unroll
        for (int q = 0; q < 4; q++) acc[w][q] = 0.f;

    const float4* Wp = reinterpret_cast<const float4*>(g_WihwT) + gq;
#pragma unroll 4
    for (int k = 0; k < KW; k++) {
        float4 wv = Wp[k * (GW / 4)];
#pragma unroll
        for (int w = 0; w < 8; w++) {
            float xv = xw[w * KW + k];
            acc[w][0] = fmaf(wv.x, xv, acc[w][0]);
            acc[w][1] = fmaf(wv.y, xv, acc[w][1]);
            acc[w][2] = fmaf(wv.z, xv, acc[w][2]);
            acc[w][3] = fmaf(wv.w, xv, acc[w][3]);
        }
    }
#pragma unroll
    for (int w = 0; w < 8; w++) {
        reinterpret_cast<float4*>(g_GXw + (size_t)(wbase + w) * GW)[gq] =
            make_float4(acc[w][0] + bias[0], acc[w][1] + bias[1],
                        acc[w][2] + bias[2], acc[w][3] + bias[3]);
    }
}

// ---------------- word LSTM recurrence: persistent, register-resident Whh ----------------
// 128 blocks x 256 threads. Warp y of block b owns hidden unit u = 8b + y.
// Barrier: blocks atomicAdd one monotonic counter (fan-in); ONLY block 0's tid0
// polls the counter and releases a single g_epoch word; all others acquire-poll
// g_epoch. Counter polling and RMW traffic no longer interfere; consumer polls
// hit one address at ~0.5 loads/cyc (unsaturated).
__global__ void __launch_bounds__(256, 1) word_lstm(const float* __restrict__ Whh_w,
                                                    float*       __restrict__ out)
{
    __shared__ float hs[HDIM];
    const int tid  = threadIdx.x;
    const int lane = tid & 31;
    const int y    = tid >> 5;
    const int u    = blockIdx.x * 8 + y;

    float w0[32], w1[32], w2[32], w3[32];
#pragma unroll
    for (int i = 0; i < 32; i++) {
        w0[i] = Whh_w[(size_t)(0 * HDIM + u) * HDIM + i * 32 + lane];
        w1[i] = Whh_w[(size_t)(1 * HDIM + u) * HDIM + i * 32 + lane];
        w2[i] = Whh_w[(size_t)(2 * HDIM + u) * HDIM + i * 32 + lane];
        w3[i] = Whh_w[(size_t)(3 * HDIM + u) * HDIM + i * 32 + lane];
    }
    float c = 0.f;

    for (int s = 0; s < S_WORDS; s++) {
        // prefetch gx_s before the barrier wait (independent of h)
        const float* gx = g_GXw + (size_t)s * GW;
        float gi0 = gx[u];
        float gf0 = gx[HDIM     + u];
        float gg0 = gx[2*HDIM   + u];
        float go0 = gx[3*HDIM   + u];

        float a0 = 0.f, a1 = 0.f, a2 = 0.f, a3 = 0.f;
        if (s > 0) {
            if (tid == 0) {
                if (blockIdx.x == 0) {
                    // aggregator: wait until all blocks arrived for step s
                    unsigned v;
                    do {
                        asm volatile("ld.acquire.gpu.global.u32 %0, [%1];"
                                     : "=r"(v) : "l"(&g_arrive));
                    } while (v < (unsigned)NBLK_WL * (unsigned)s);
                    asm volatile("st.release.gpu.global.s32 [%0], %1;"
                                 :: "l"(&g_epoch[0]), "r"(s) : "memory");
                } else {
                    int e;
                    do {
                        asm volatile("ld.acquire.gpu.global.s32 %0, [%1];"
                                     : "=r"(e) : "l"(&g_epoch[0]));
                    } while (e < s);
                }
            }
            __syncthreads();
            // coalesced, pipelined reload of h_{s-1} from L2 into smem
            const float* hb = g_hbuf + ((s - 1) & 1) * HDIM;
#pragma unroll
            for (int k = 0; k < 4; k++)
                hs[k * 256 + tid] = __ldcg(hb + k * 256 + tid);
            __syncthreads();

#pragma unroll
            for (int i = 0; i < 32; i++) {
                float hv = hs[i * 32 + lane];
                a0 = fmaf(w0[i], hv, a0);
                a1 = fmaf(w1[i], hv, a1);
                a2 = fmaf(w2[i], hv, a2);
                a3 = fmaf(w3[i], hv, a3);
            }
        }
#pragma unroll
        for (int off = 16; off > 0; off >>= 1) {
            a0 += __shfl_xor_sync(0xffffffffu, a0, off);
            a1 += __shfl_xor_sync(0xffffffffu, a1, off);
            a2 += __shfl_xor_sync(0xffffffffu, a2, off);
            a3 += __shfl_xor_sync(0xffffffffu, a3, off);
        }

        float cn = sigf(gf0 + a1) * c + sigf(gi0 + a0) * tanhf(gg0 + a2);
        c = cn;
        float h = sigf(go0 + a3) * tanhf(cn);

        if (lane == 0) {
            out[(size_t)s * HDIM + u] = h;
            g_hbuf[(s & 1) * HDIM + u] = h;
        }
        __syncthreads();
        if (s < S_WORDS - 1 && tid == 0) {
            __threadfence();            // release the 8 h stores (ordered via bar)
            atomicAdd(&g_arrive, 1u);   // arrive for step s+1
        }
    }
}

// ---------------- launch ----------------
extern "C" void kernel_launch(void* const* d_in, const int* in_sizes, int n_in,
                              void* d_out, int out_size)
{
    const int*   word_idxs = (const int*)  d_in[0];
    const int*   char_idxs = (const int*)  d_in[1];
    const int*   char_lens = (const int*)  d_in[2];
    const float* char_emb  = (const float*)d_in[3];
    const float* word_emb  = (const float*)d_in[4];
    const float* Wih_c     = (const float*)d_in[5];
    const float* Whh_c     = (const float*)d_in[6];
    const float* bih_c     = (const float*)d_in[7];
    const float* bhh_c     = (const float*)d_in[8];
    const float* Wih_w     = (const float*)d_in[9];
    const float* Whh_w     = (const float*)d_in[10];
    const float* bih_w     = (const float*)d_in[11];
    const float* bhh_w     = (const float*)d_in[12];
    float* out = (float*)d_out;

    const int char_smem = (CWPB * KC + CWPB * GC) * (int)sizeof(float);  // 98304 B
    const int gemm_smem = 8 * KW * (int)sizeof(float);                   // 24576 B
    cudaFuncSetAttribute(char_lstm, cudaFuncAttributeMaxDynamicSharedMemorySize, char_smem);
    cudaFuncSetAttribute(word_gemm, cudaFuncAttributeMaxDynamicSharedMemorySize, gemm_smem);

    prep_c<<<(KC * GC + 255) / 256, 256>>>(Wih_c, Whh_c);
    prep_w<<<(KW * GW + 255) / 256, 256>>>(Wih_w);   // also resets g_arrive/g_epoch

    char_lstm<<<S_WORDS / CWPB, 256, char_smem>>>(char_idxs, char_lens, char_emb, bih_c, bhh_c);

    word_gemm<<<dim3(S_WORDS / 8, 4), 256, gemm_smem>>>(word_idxs, word_emb, bih_w, bhh_w);

    word_lstm<<<NBLK_WL, 256>>>(Whh_w, out);
}

// round 8
// speedup vs baseline: 1.4328x; 1.0262x over previous
#include <cuda_runtime.h>
#include <cuda_bf16.h>
#include <math.h>

#define S_WORDS 2048
#define LMAX    16
#define CE      256
#define WE      512
#define HDIM    1024
#define GC      (4*CE)     // 1024 gate rows, char LSTM
#define GW      (4*HDIM)   // 4096 gate rows, word LSTM
#define KC      (2*CE)     // 512  (x | h) for char LSTM
#define KW      (WE+CE)    // 768  (we | char_feat)
#define NBLK_WL 128        // persistent blocks for word LSTM (<= 148 SMs)
#define CWPB    16         // words per block, char LSTM

// ---------------- device scratch (no allocations allowed) ----------------
__device__ float g_WcT[KC*GC];        // [k=512][g=1024] transposed char weights
__device__ float g_WihwT[KW*GW];      // [k=768][g=4096] transposed word input weights
__device__ float g_lasth[S_WORDS*CE]; // char-LSTM output feature per word
__device__ float g_GXw[S_WORDS*GW];   // precomputed x-part of word-LSTM gates (+bias)
// tagged h broadcast: high 32 bits = step tag, low 32 bits = h bits. Double-buffered.
__device__ unsigned long long g_hpair[2*HDIM];

__device__ __forceinline__ float sigf(float x) { return 1.f / (1.f + __expf(-x)); }

// ---------------- prep: transpose weights, reset tags ----------------
__global__ void prep_c(const float* __restrict__ Wih_c, const float* __restrict__ Whh_c) {
    int idx = blockIdx.x * blockDim.x + threadIdx.x;
    if (idx >= KC * GC) return;
    int k = idx / GC, g = idx % GC;
    g_WcT[idx] = (k < CE) ? Wih_c[g * CE + k] : Whh_c[g * CE + (k - CE)];
}

__global__ void prep_w(const float* __restrict__ Wih_w) {
    int idx = blockIdx.x * blockDim.x + threadIdx.x;
    if (idx < 2 * HDIM) g_hpair[idx] = 0xFFFFFFFF00000000ull;   // tag = -1
    if (idx >= KW * GW) return;
    int k = idx / GW, g = idx % GW;
    g_WihwT[idx] = Wih_w[g * KW + k];
}

// ---------------- char LSTM: 16 words per block, 16 timesteps ----------------
__global__ void __launch_bounds__(256) char_lstm(
    const int*   __restrict__ char_idxs,
    const int*   __restrict__ char_lens,
    const float* __restrict__ char_emb,
    const float* __restrict__ bih_c,
    const float* __restrict__ bhh_c)
{
    extern __shared__ float sm[];
    float* xh    = sm;               // CWPB*512
    float* gates = sm + CWPB * KC;   // CWPB*1024
    const int tid   = threadIdx.x;      // 0..255
    const int wbase = blockIdx.x * CWPB;

    float bias[4];
#pragma unroll
    for (int q = 0; q < 4; q++) bias[q] = bih_c[4 * tid + q] + bhh_c[4 * tid + q];

    float c[CWPB];
    int   len[CWPB];
#pragma unroll
    for (int w = 0; w < CWPB; w++) {
        c[w]  = 0.f;
        len[w] = char_lens[wbase + w];
        xh[w * KC + CE + tid] = 0.f;   // h = 0
    }
    __syncthreads();

    const float4* Wp = reinterpret_cast<const float4*>(g_WcT) + tid;  // column block 4*tid

    for (int t = 0; t < LMAX; t++) {
#pragma unroll
        for (int w = 0; w < CWPB; w++) {
            int ci = char_idxs[(wbase + w) * LMAX + t];
            xh[w * KC + tid] = char_emb[ci * CE + tid];
        }
        __syncthreads();

        float acc[CWPB][4];
#pragma unroll
        for (int w = 0; w < CWPB; w++)
#pragma unroll
            for (int q = 0; q < 4; q++) acc[w][q] = 0.f;

#pragma unroll 2
        for (int k = 0; k < KC; k++) {
            float4 wv = Wp[k * (GC / 4)];
#pragma unroll
            for (int w = 0; w < CWPB; w++) {
                float xv = xh[w * KC + k];
                acc[w][0] = fmaf(wv.x, xv, acc[w][0]);
                acc[w][1] = fmaf(wv.y, xv, acc[w][1]);
                acc[w][2] = fmaf(wv.z, xv, acc[w][2]);
                acc[w][3] = fmaf(wv.w, xv, acc[w][3]);
            }
        }
#pragma unroll
        for (int w = 0; w < CWPB; w++) {
            reinterpret_cast<float4*>(gates + w * GC)[tid] =
                make_float4(acc[w][0] + bias[0], acc[w][1] + bias[1],
                            acc[w][2] + bias[2], acc[w][3] + bias[3]);
        }
        __syncthreads();

#pragma unroll
        for (int w = 0; w < CWPB; w++) {
            float ig = gates[w * GC +            tid];
            float fg = gates[w * GC +     CE +   tid];
            float gg = gates[w * GC + 2 * CE +   tid];
            float og = gates[w * GC + 3 * CE +   tid];
            float cn = sigf(fg) * c[w] + sigf(ig) * tanhf(gg);
            float hn = sigf(og) * tanhf(cn);
            c[w] = cn;
            xh[w * KC + CE + tid] = hn;
            if (t == len[w] - 1) g_lasth[(wbase + w) * CE + tid] = hn;
        }
        __syncthreads();
    }
}

// ---------------- word-LSTM input GEMM: GXw = [we|last] @ Wih_w^T + bias ----------------
__global__ void word_gemm(const int*   __restrict__ word_idxs,
                          const float* __restrict__ word_emb,
                          const float* __restrict__ bih_w,
                          const float* __restrict__ bhh_w)
{
    extern __shared__ float xw[];   // [8][768]
    const int tid   = threadIdx.x;           // 0..255
    const int wbase = blockIdx.x * 8;
    const int gq    = blockIdx.y * 256 + tid; // float4 column index 0..1023

#pragma unroll
    for (int w = 0; w < 8; w++) {
        int wi = word_idxs[wbase + w];
        xw[w * KW +       tid] = word_emb[wi * WE +       tid];
        xw[w * KW + 256 + tid] = word_emb[wi * WE + 256 + tid];
        xw[w * KW + 512 + tid] = g_lasth[(wbase + w) * CE + tid];
    }
    __syncthreads();

    const int gbase = 4 * gq;
    float bias[4];
#pragma unroll
    for (int q = 0; q < 4; q++) bias[q] = bih_w[gbase + q] + bhh_w[gbase + q];

    float acc[8][4];
#pragma unroll
    for (int w = 0; w < 8; w++)
#pragma unroll
        for (int q = 0; q < 4; q++) acc[w][q] = 0.f;

    const float4* Wp = reinterpret_cast<const float4*>(g_WihwT) + gq;
#pragma unroll 4
    for (int k = 0; k < KW; k++) {
        float4 wv = Wp[k * (GW / 4)];
#pragma unroll
        for (int w = 0; w < 8; w++) {
            float xv = xw[w * KW + k];
            acc[w][0] = fmaf(wv.x, xv, acc[w][0]);
            acc[w][1] = fmaf(wv.y, xv, acc[w][1]);
            acc[w][2] = fmaf(wv.z, xv, acc[w][2]);
            acc[w][3] = fmaf(wv.w, xv, acc[w][3]);
        }
    }
#pragma unroll
    for (int w = 0; w < 8; w++) {
        reinterpret_cast<float4*>(g_GXw + (size_t)(wbase + w) * GW)[gq] =
            make_float4(acc[w][0] + bias[0], acc[w][1] + bias[1],
                        acc[w][2] + bias[2], acc[w][3] + bias[3]);
    }
}

// ---------------- word LSTM recurrence: tagged-data sync ----------------
// 128 blocks x 256 threads. Warp y of block b owns hidden unit u = 8b + y.
// Producer publishes (tag=s | h_bits) in one relaxed 8B store; consumers poll
// those words directly (tag==s-1) — the signal IS the data. No fence, no
// atomic, no aggregator. Double-buffered pair array + exact tag match make
// overwrite-before-read impossible.
__global__ void __launch_bounds__(256, 1) word_lstm(const float* __restrict__ Whh_w,
                                                    float*       __restrict__ out)
{
    __shared__ float hs[2][HDIM];
    const int tid  = threadIdx.x;
    const int lane = tid & 31;
    const int y    = tid >> 5;
    const int u    = blockIdx.x * 8 + y;

    float w0[32], w1[32], w2[32], w3[32];
#pragma unroll
    for (int i = 0; i < 32; i++) {
        w0[i] = Whh_w[(size_t)(0 * HDIM + u) * HDIM + i * 32 + lane];
        w1[i] = Whh_w[(size_t)(1 * HDIM + u) * HDIM + i * 32 + lane];
        w2[i] = Whh_w[(size_t)(2 * HDIM + u) * HDIM + i * 32 + lane];
        w3[i] = Whh_w[(size_t)(3 * HDIM + u) * HDIM + i * 32 + lane];
    }
    float c = 0.f;

    for (int s = 0; s < S_WORDS; s++) {
        // prefetch gx_s (independent of h)
        const float* gx = g_GXw + (size_t)s * GW;
        float gi0 = gx[u];
        float gf0 = gx[HDIM     + u];
        float gg0 = gx[2*HDIM   + u];
        float go0 = gx[3*HDIM   + u];

        float a0 = 0.f, a1 = 0.f, a2 = 0.f, a3 = 0.f;
        if (s > 0) {
            const int want = s - 1;
            const int slot = want & 1;
            // each thread polls 4 pairs (coalesced: warp covers 32 consecutive)
#pragma unroll
            for (int j = 0; j < 4; j++) {
                const int p = j * 256 + tid;
                const unsigned long long* ap = g_hpair + slot * HDIM + p;
                unsigned long long v;
                asm volatile("ld.relaxed.gpu.global.b64 %0, [%1];" : "=l"(v) : "l"(ap));
                while ((int)(v >> 32) != want) {
                    __nanosleep(32);
                    asm volatile("ld.relaxed.gpu.global.b64 %0, [%1];" : "=l"(v) : "l"(ap));
                }
                hs[slot][p] = __uint_as_float((unsigned)v);
            }
            __syncthreads();

#pragma unroll
            for (int i = 0; i < 32; i++) {
                float hv = hs[slot][i * 32 + lane];
                a0 = fmaf(w0[i], hv, a0);
                a1 = fmaf(w1[i], hv, a1);
                a2 = fmaf(w2[i], hv, a2);
                a3 = fmaf(w3[i], hv, a3);
            }
        }
#pragma unroll
        for (int off = 16; off > 0; off >>= 1) {
            a0 += __shfl_xor_sync(0xffffffffu, a0, off);
            a1 += __shfl_xor_sync(0xffffffffu, a1, off);
            a2 += __shfl_xor_sync(0xffffffffu, a2, off);
            a3 += __shfl_xor_sync(0xffffffffu, a3, off);
        }

        float cn = sigf(gf0 + a1) * c + sigf(gi0 + a0) * tanhf(gg0 + a2);
        c = cn;
        float h = sigf(go0 + a3) * tanhf(cn);

        if (lane == 0) {
            out[(size_t)s * HDIM + u] = h;
            if (s < S_WORDS - 1) {
                unsigned long long pv =
                    ((unsigned long long)(unsigned)s << 32) | (unsigned long long)__float_as_uint(h);
                const unsigned long long* ap = g_hpair + (s & 1) * HDIM + u;
                asm volatile("st.relaxed.gpu.global.b64 [%0], %1;" :: "l"(ap), "l"(pv) : "memory");
            }
        }
        // no trailing bar: next step's smem writes go to the other hs slot,
        // and the per-step __syncthreads above provides the WAR protection.
    }
}

// ---------------- launch ----------------
extern "C" void kernel_launch(void* const* d_in, const int* in_sizes, int n_in,
                              void* d_out, int out_size)
{
    const int*   word_idxs = (const int*)  d_in[0];
    const int*   char_idxs = (const int*)  d_in[1];
    const int*   char_lens = (const int*)  d_in[2];
    const float* char_emb  = (const float*)d_in[3];
    const float* word_emb  = (const float*)d_in[4];
    const float* Wih_c     = (const float*)d_in[5];
    const float* Whh_c     = (const float*)d_in[6];
    const float* bih_c     = (const float*)d_in[7];
    const float* bhh_c     = (const float*)d_in[8];
    const float* Wih_w     = (const float*)d_in[9];
    const float* Whh_w     = (const float*)d_in[10];
    const float* bih_w     = (const float*)d_in[11];
    const float* bhh_w     = (const float*)d_in[12];
    float* out = (float*)d_out;

    const int char_smem = (CWPB * KC + CWPB * GC) * (int)sizeof(float);  // 98304 B
    const int gemm_smem = 8 * KW * (int)sizeof(float);                   // 24576 B
    cudaFuncSetAttribute(char_lstm, cudaFuncAttributeMaxDynamicSharedMemorySize, char_smem);
    cudaFuncSetAttribute(word_gemm, cudaFuncAttributeMaxDynamicSharedMemorySize, gemm_smem);

    prep_c<<<(KC * GC + 255) / 256, 256>>>(Wih_c, Whh_c);
    prep_w<<<(KW * GW + 255) / 256, 256>>>(Wih_w);   // also resets g_hpair tags

    char_lstm<<<S_WORDS / CWPB, 256, char_smem>>>(char_idxs, char_lens, char_emb, bih_c, bhh_c);

    word_gemm<<<dim3(S_WORDS / 8, 4), 256, gemm_smem>>>(word_idxs, word_emb, bih_w, bhh_w);

    word_lstm<<<NBLK_WL, 256>>>(Whh_w, out);
}

// round 9
// speedup vs baseline: 2.2031x; 1.5376x over previous
#include <cuda_runtime.h>
#include <cuda_bf16.h>
#include <math.h>

#define S_WORDS 2048
#define LMAX    16
#define CE      256
#define WE      512
#define HDIM    1024
#define GC      (4*CE)     // 1024 gate rows, char LSTM
#define GW      (4*HDIM)   // 4096 gate rows, word LSTM
#define KC      (2*CE)     // 512  (x | h) for char LSTM
#define KW      (WE+CE)    // 768  (we | char_feat)
#define NBLK_WL 128        // persistent blocks for word LSTM (<= 148 SMs)
#define CWPB    16         // words per block, char LSTM

// ---------------- device scratch (no allocations allowed) ----------------
__device__ float g_WcT[KC*GC];        // [k=512][g=1024] transposed char weights
__device__ float g_WihwT[KW*GW];      // [k=768][g=4096] transposed word input weights
__device__ float g_lasth[S_WORDS*CE]; // char-LSTM output feature per word
__device__ float g_GXw[S_WORDS*GW];   // precomputed x-part of word-LSTM gates (+bias)
// tagged h broadcast: high 32 bits = step tag, low 32 bits = h bits. Double-buffered.
__device__ unsigned long long g_hpair[2*HDIM];

__device__ __forceinline__ float sigf(float x) { return 1.f / (1.f + __expf(-x)); }

// ---------------- prep: transpose weights, reset tags ----------------
__global__ void prep_c(const float* __restrict__ Wih_c, const float* __restrict__ Whh_c) {
    int idx = blockIdx.x * blockDim.x + threadIdx.x;
    if (idx >= KC * GC) return;
    int k = idx / GC, g = idx % GC;
    g_WcT[idx] = (k < CE) ? Wih_c[g * CE + k] : Whh_c[g * CE + (k - CE)];
}

__global__ void prep_w(const float* __restrict__ Wih_w) {
    int idx = blockIdx.x * blockDim.x + threadIdx.x;
    if (idx < 2 * HDIM) g_hpair[idx] = 0xFFFFFFFF00000000ull;   // tag = -1
    if (idx >= KW * GW) return;
    int k = idx / GW, g = idx % GW;
    g_WihwT[idx] = Wih_w[g * KW + k];
}

// ---------------- char LSTM: 16 words per block, 16 timesteps ----------------
__global__ void __launch_bounds__(256) char_lstm(
    const int*   __restrict__ char_idxs,
    const int*   __restrict__ char_lens,
    const float* __restrict__ char_emb,
    const float* __restrict__ bih_c,
    const float* __restrict__ bhh_c)
{
    extern __shared__ float sm[];
    float* xh    = sm;               // CWPB*512
    float* gates = sm + CWPB * KC;   // CWPB*1024
    const int tid   = threadIdx.x;      // 0..255
    const int wbase = blockIdx.x * CWPB;

    float bias[4];
#pragma unroll
    for (int q = 0; q < 4; q++) bias[q] = bih_c[4 * tid + q] + bhh_c[4 * tid + q];

    float c[CWPB];
    int   len[CWPB];
#pragma unroll
    for (int w = 0; w < CWPB; w++) {
        c[w]  = 0.f;
        len[w] = char_lens[wbase + w];
        xh[w * KC + CE + tid] = 0.f;   // h = 0
    }
    __syncthreads();

    const float4* Wp = reinterpret_cast<const float4*>(g_WcT) + tid;  // column block 4*tid

    for (int t = 0; t < LMAX; t++) {
#pragma unroll
        for (int w = 0; w < CWPB; w++) {
            int ci = char_idxs[(wbase + w) * LMAX + t];
            xh[w * KC + tid] = char_emb[ci * CE + tid];
        }
        __syncthreads();

        float acc[CWPB][4];
#pragma unroll
        for (int w = 0; w < CWPB; w++)
#pragma unroll
            for (int q = 0; q < 4; q++) acc[w][q] = 0.f;

#pragma unroll 2
        for (int k = 0; k < KC; k++) {
            float4 wv = Wp[k * (GC / 4)];
#pragma unroll
            for (int w = 0; w < CWPB; w++) {
                float xv = xh[w * KC + k];
                acc[w][0] = fmaf(wv.x, xv, acc[w][0]);
                acc[w][1] = fmaf(wv.y, xv, acc[w][1]);
                acc[w][2] = fmaf(wv.z, xv, acc[w][2]);
                acc[w][3] = fmaf(wv.w, xv, acc[w][3]);
            }
        }
#pragma unroll
        for (int w = 0; w < CWPB; w++) {
            reinterpret_cast<float4*>(gates + w * GC)[tid] =
                make_float4(acc[w][0] + bias[0], acc[w][1] + bias[1],
                            acc[w][2] + bias[2], acc[w][3] + bias[3]);
        }
        __syncthreads();

#pragma unroll
        for (int w = 0; w < CWPB; w++) {
            float ig = gates[w * GC +            tid];
            float fg = gates[w * GC +     CE +   tid];
            float gg = gates[w * GC + 2 * CE +   tid];
            float og = gates[w * GC + 3 * CE +   tid];
            float cn = sigf(fg) * c[w] + sigf(ig) * tanhf(gg);
            float hn = sigf(og) * tanhf(cn);
            c[w] = cn;
            xh[w * KC + CE + tid] = hn;
            if (t == len[w] - 1) g_lasth[(wbase + w) * CE + tid] = hn;
        }
        __syncthreads();
    }
}

// ---------------- word-LSTM input GEMM: GXw = [we|last] @ Wih_w^T + bias ----------------
__global__ void word_gemm(const int*   __restrict__ word_idxs,
                          const float* __restrict__ word_emb,
                          const float* __restrict__ bih_w,
                          const float* __restrict__ bhh_w)
{
    extern __shared__ float xw[];   // [8][768]
    const int tid   = threadIdx.x;           // 0..255
    const int wbase = blockIdx.x * 8;
    const int gq    = blockIdx.y * 256 + tid; // float4 column index 0..1023

#pragma unroll
    for (int w = 0; w < 8; w++) {
        int wi = word_idxs[wbase + w];
        xw[w * KW +       tid] = word_emb[wi * WE +       tid];
        xw[w * KW + 256 + tid] = word_emb[wi * WE + 256 + tid];
        xw[w * KW + 512 + tid] = g_lasth[(wbase + w) * CE + tid];
    }
    __syncthreads();

    const int gbase = 4 * gq;
    float bias[4];
#pragma unroll
    for (int q = 0; q < 4; q++) bias[q] = bih_w[gbase + q] + bhh_w[gbase + q];

    float acc[8][4];
#pragma unroll
    for (int w = 0; w < 8; w++)
#pragma unroll
        for (int q = 0; q < 4; q++) acc[w][q] = 0.f;

    const float4* Wp = reinterpret_cast<const float4*>(g_WihwT) + gq;
#pragma unroll 4
    for (int k = 0; k < KW; k++) {
        float4 wv = Wp[k * (GW / 4)];
#pragma unroll
        for (int w = 0; w < 8; w++) {
            float xv = xw[w * KW + k];
            acc[w][0] = fmaf(wv.x, xv, acc[w][0]);
            acc[w][1] = fmaf(wv.y, xv, acc[w][1]);
            acc[w][2] = fmaf(wv.z, xv, acc[w][2]);
            acc[w][3] = fmaf(wv.w, xv, acc[w][3]);
        }
    }
#pragma unroll
    for (int w = 0; w < 8; w++) {
        reinterpret_cast<float4*>(g_GXw + (size_t)(wbase + w) * GW)[gq] =
            make_float4(acc[w][0] + bias[0], acc[w][1] + bias[1],
                        acc[w][2] + bias[2], acc[w][3] + bias[3]);
    }
}

// ---------------- word LSTM recurrence: tagged-data sync, batched polling ----------------
// 128 blocks x 256 threads. Warp y of block b owns hidden unit u = 8b + y.
// Producer publishes (tag=s | h_bits) in one relaxed 8B store; each consumer
// thread polls its 4 pair words with BATCHED loads (MLP=4, one L2 round trip
// per poll round), re-issuing only unsatisfied slots. No sleep on the fast
// path; nanosleep kicks in only after 16 failed rounds.
__global__ void __launch_bounds__(256, 1) word_lstm(const float* __restrict__ Whh_w,
                                                    float*       __restrict__ out)
{
    __shared__ float hs[2][HDIM];
    const int tid  = threadIdx.x;
    const int lane = tid & 31;
    const int y    = tid >> 5;
    const int u    = blockIdx.x * 8 + y;

    float w0[32], w1[32], w2[32], w3[32];
#pragma unroll
    for (int i = 0; i < 32; i++) {
        w0[i] = Whh_w[(size_t)(0 * HDIM + u) * HDIM + i * 32 + lane];
        w1[i] = Whh_w[(size_t)(1 * HDIM + u) * HDIM + i * 32 + lane];
        w2[i] = Whh_w[(size_t)(2 * HDIM + u) * HDIM + i * 32 + lane];
        w3[i] = Whh_w[(size_t)(3 * HDIM + u) * HDIM + i * 32 + lane];
    }
    float c = 0.f;

    for (int s = 0; s < S_WORDS; s++) {
        // prefetch gx_s (independent of h)
        const float* gx = g_GXw + (size_t)s * GW;
        float gi0 = gx[u];
        float gf0 = gx[HDIM     + u];
        float gg0 = gx[2*HDIM   + u];
        float go0 = gx[3*HDIM   + u];

        float a0 = 0.f, a1 = 0.f, a2 = 0.f, a3 = 0.f;
        if (s > 0) {
            const int want = s - 1;
            const int slot = want & 1;
            const unsigned long long* base = g_hpair + slot * HDIM + tid;

            unsigned long long v0, v1, v2, v3;
            unsigned done = 0;
            int rounds = 0;
            do {
                // issue all unsatisfied loads back-to-back (MLP up to 4)
                if (!(done & 1u))
                    asm volatile("ld.relaxed.gpu.global.b64 %0, [%1];" : "=l"(v0) : "l"(base));
                if (!(done & 2u))
                    asm volatile("ld.relaxed.gpu.global.b64 %0, [%1];" : "=l"(v1) : "l"(base + 256));
                if (!(done & 4u))
                    asm volatile("ld.relaxed.gpu.global.b64 %0, [%1];" : "=l"(v2) : "l"(base + 512));
                if (!(done & 8u))
                    asm volatile("ld.relaxed.gpu.global.b64 %0, [%1];" : "=l"(v3) : "l"(base + 768));
                if ((int)(v0 >> 32) == want) done |= 1u;
                if ((int)(v1 >> 32) == want) done |= 2u;
                if ((int)(v2 >> 32) == want) done |= 4u;
                if ((int)(v3 >> 32) == want) done |= 8u;
                if (done == 15u) break;
                if (++rounds > 16) __nanosleep(64);   // safety valve only
            } while (true);

            hs[slot][tid      ] = __uint_as_float((unsigned)v0);
            hs[slot][tid + 256] = __uint_as_float((unsigned)v1);
            hs[slot][tid + 512] = __uint_as_float((unsigned)v2);
            hs[slot][tid + 768] = __uint_as_float((unsigned)v3);
            __syncthreads();

#pragma unroll
            for (int i = 0; i < 32; i++) {
                float hv = hs[slot][i * 32 + lane];
                a0 = fmaf(w0[i], hv, a0);
                a1 = fmaf(w1[i], hv, a1);
                a2 = fmaf(w2[i], hv, a2);
                a3 = fmaf(w3[i], hv, a3);
            }
        }
#pragma unroll
        for (int off = 16; off > 0; off >>= 1) {
            a0 += __shfl_xor_sync(0xffffffffu, a0, off);
            a1 += __shfl_xor_sync(0xffffffffu, a1, off);
            a2 += __shfl_xor_sync(0xffffffffu, a2, off);
            a3 += __shfl_xor_sync(0xffffffffu, a3, off);
        }

        float cn = sigf(gf0 + a1) * c + sigf(gi0 + a0) * tanhf(gg0 + a2);
        c = cn;
        float h = sigf(go0 + a3) * tanhf(cn);

        if (lane == 0) {
            out[(size_t)s * HDIM + u] = h;
            if (s < S_WORDS - 1) {
                unsigned long long pv =
                    ((unsigned long long)(unsigned)s << 32) | (unsigned long long)__float_as_uint(h);
                const unsigned long long* ap = g_hpair + (s & 1) * HDIM + u;
                asm volatile("st.relaxed.gpu.global.b64 [%0], %1;" :: "l"(ap), "l"(pv) : "memory");
            }
        }
        // no trailing bar: next step's smem writes go to the other hs slot,
        // and the per-step __syncthreads above provides the WAR protection.
    }
}

// ---------------- launch ----------------
extern "C" void kernel_launch(void* const* d_in, const int* in_sizes, int n_in,
                              void* d_out, int out_size)
{
    const int*   word_idxs = (const int*)  d_in[0];
    const int*   char_idxs = (const int*)  d_in[1];
    const int*   char_lens = (const int*)  d_in[2];
    const float* char_emb  = (const float*)d_in[3];
    const float* word_emb  = (const float*)d_in[4];
    const float* Wih_c     = (const float*)d_in[5];
    const float* Whh_c     = (const float*)d_in[6];
    const float* bih_c     = (const float*)d_in[7];
    const float* bhh_c     = (const float*)d_in[8];
    const float* Wih_w     = (const float*)d_in[9];
    const float* Whh_w     = (const float*)d_in[10];
    const float* bih_w     = (const float*)d_in[11];
    const float* bhh_w     = (const float*)d_in[12];
    float* out = (float*)d_out;

    const int char_smem = (CWPB * KC + CWPB * GC) * (int)sizeof(float);  // 98304 B
    const int gemm_smem = 8 * KW * (int)sizeof(float);                   // 24576 B
    cudaFuncSetAttribute(char_lstm, cudaFuncAttributeMaxDynamicSharedMemorySize, char_smem);
    cudaFuncSetAttribute(word_gemm, cudaFuncAttributeMaxDynamicSharedMemorySize, gemm_smem);

    prep_c<<<(KC * GC + 255) / 256, 256>>>(Wih_c, Whh_c);
    prep_w<<<(KW * GW + 255) / 256, 256>>>(Wih_w);   // also resets g_hpair tags

    char_lstm<<<S_WORDS / CWPB, 256, char_smem>>>(char_idxs, char_lens, char_emb, bih_c, bhh_c);

    word_gemm<<<dim3(S_WORDS / 8, 4), 256, gemm_smem>>>(word_idxs, word_emb, bih_w, bhh_w);

    word_lstm<<<NBLK_WL, 256>>>(Whh_w, out);
}